// round 7
// baseline (speedup 1.0000x reference)
#include <cuda_runtime.h>
#include <stdint.h>
#include <stddef.h>

#define N_NODES 10000
#define DIM 40
#define KSEL 32
#define ALPHA 3.0f
#define JTILE 64
#define RPB 8                       // rows per mega block (one warp per row)
#define NGROUPS (N_NODES / RPB)     // 1250 blocks
#define CROWS 40                    // prep rows per chunk
#define NCHUNK ((N_NODES + CROWS - 1) / CROWS)   // 250 chunks

// ---------------- device scratch (no allocation allowed) ----------------
__device__ float g_P[N_NODES * DIM];
__device__ float g_Q[N_NODES * DIM];
__device__ int   g_fail[N_NODES];
__device__ int   g_nfail = 0;
__device__ int   g_claim = 0;   // prep chunk claim counter
__device__ int   g_c1    = 0;   // prep chunks completed
__device__ int   g_c2    = 0;   // mega blocks completed

// ---------------- XLA EmitFastTanh replica (with-FMA variant) ----------------
__device__ __forceinline__ float xla_tanh(float x) {
    const float kClamp = 7.99881172180175781f;
    float ax = fabsf(x);
    float xc = fminf(fmaxf(x, -kClamp), kClamp);
    float x2 = xc * xc;
    float num = -2.76076847742355e-16f;
    num = fmaf(x2, num,  2.00018790482477e-13f);
    num = fmaf(x2, num, -8.60467152213735e-11f);
    num = fmaf(x2, num,  5.12229709037114e-08f);
    num = fmaf(x2, num,  1.48572235717979e-05f);
    num = fmaf(x2, num,  6.37261928875436e-04f);
    num = fmaf(x2, num,  4.89352455891786e-03f);
    num = xc * num;
    float den = 1.19825839466702e-06f;
    den = fmaf(x2, den, 1.18534705686654e-04f);
    den = fmaf(x2, den, 2.26843463243900e-03f);
    den = fmaf(x2, den, 4.89352518554385e-03f);
    float r = num / den;
    return (ax < 0.0004f) ? x : r;
}

// ---------------- mega: claim-prep + zero own rows + scan + scatter ----------------
__global__ void __launch_bounds__(256) mega_kernel(
        const int* __restrict__ idx,
        const float* __restrict__ emb1,
        const float* __restrict__ emb2,
        const float* __restrict__ W1,
        const float* __restrict__ b1,
        const float* __restrict__ W2,
        const float* __restrict__ b2,
        float* __restrict__ out) {
    __shared__ float sW1t[DIM * DIM];          // [k][d]
    __shared__ float sW2t[DIM * DIM];
    __shared__ float sb2[2 * DIM];
    __shared__ float tP[DIM][JTILE];           // scan tiles; reused for prep staging
    __shared__ float tQ[DIM][JTILE];
    __shared__ float sP[RPB][DIM];
    __shared__ float sQ[RPB][DIM];
    __shared__ int s_done, s_chunk, s_may;

    const int tid  = threadIdx.x;
    const int lane = tid & 31;
    const int w    = tid >> 5;
    const int bid  = blockIdx.x;
    const int row0 = bid * RPB;
    const int row  = row0 + w;

    // ---- phase 1: claim and execute prep chunks while any remain ----
    if (tid == 0) s_may = (*(volatile int*)&g_claim) < NCHUNK;
    __syncthreads();

    if (s_may) {
        for (int e = tid; e < DIM * DIM; e += 256) {
            int d = e / DIM, k = e % DIM;
            sW1t[k * DIM + d] = W1[e];
            sW2t[k * DIM + d] = W2[e];
        }
        if (tid < 2 * DIM)
            sb2[tid] = (tid < DIM) ? b1[tid] : b2[tid - DIM];
        __syncthreads();

        float* pe1 = &tP[0][0];   // CROWS*DIM = 1600 <= 2560 floats
        float* pe2 = &tQ[0][0];
        while (true) {
            if (tid == 0) s_chunk = atomicAdd(&g_claim, 1);
            __syncthreads();
            const int c = s_chunk;
            if (c >= NCHUNK) break;
            const int pr0 = c * CROWS;
            int nr = N_NODES - pr0; if (nr > CROWS) nr = CROWS;

            for (int e = tid; e < nr * DIM; e += 256) {
                int i = e / DIM, k = e % DIM;
                int s = idx[pr0 + i];
                pe1[e] = emb1[(size_t)s * DIM + k];
                pe2[e] = emb2[(size_t)s * DIM + k];
            }
            __syncthreads();
            for (int e = tid; e < nr * DIM; e += 256) {
                int i = e / DIM, d = e % DIM;
                float z1 = 0.f, z2 = 0.f;
#pragma unroll
                for (int k = 0; k < DIM; k++) {
                    z1 = fmaf(pe1[i * DIM + k], sW1t[k * DIM + d], z1);
                    z2 = fmaf(pe2[i * DIM + k], sW2t[k * DIM + d], z2);
                }
                g_P[(pr0 + i) * DIM + d] = xla_tanh(ALPHA * (z1 + sb2[d]));
                g_Q[(pr0 + i) * DIM + d] = xla_tanh(ALPHA * (z2 + sb2[DIM + d]));
            }
            __threadfence();
            __syncthreads();
            if (tid == 0) atomicAdd(&g_c1, 1);
        }
    }

    // ---- phase 2: zero this block's 8 output rows (independent of prep) ----
    {
        float4* o4 = reinterpret_cast<float4*>(out + (size_t)row0 * N_NODES);
        const float4 z = make_float4(0.f, 0.f, 0.f, 0.f);
        for (int i = tid; i < RPB * N_NODES / 4; i += 256)
            __stcs(&o4[i], z);
    }

    // ---- phase 3: gate on all prep chunks complete (expected already) ----
    if (tid == 0) {
        volatile int* c = &g_c1;
        while (*c < NCHUNK) __nanosleep(64);
    }
    __syncthreads();
    __threadfence();

    // ---- phase 4: stage own rows, scan, direct scatter ----
    for (int e = tid; e < RPB * DIM; e += 256) {
        int r = e / DIM, k = e % DIM;
        sP[r][k] = g_P[(row0 + r) * DIM + k];
        sQ[r][k] = g_Q[(row0 + r) * DIM + k];
    }
    if (tid == 0) s_done = 0;
    __syncthreads();

    float rP[DIM], rQ[DIM];
#pragma unroll
    for (int k = 0; k < DIM; k++) { rP[k] = sP[w][k]; rQ[k] = sQ[w][k]; }

    const float C = xla_tanh(8.0f);
    int  hits = 0;
    bool done = false;
    const int ntiles = (N_NODES + JTILE - 1) / JTILE;

    for (int t = 0; t < ntiles; t++) {
        const int j0 = t * JTILE;
        for (int e = tid; e < DIM * JTILE; e += 256) {
            int k = e / JTILE, j = e % JTILE;
            int gj = j0 + j;
            float vp = 0.f, vq = 0.f;
            if (gj < N_NODES) {
                vp = g_P[gj * DIM + k];
                vq = g_Q[gj * DIM + k];
            }
            tP[k][j] = vp;
            tQ[k][j] = vq;
        }
        __syncthreads();

        if (!done) {
#pragma unroll
            for (int q = 0; q < JTILE / 32; q++) {
                const int jt = q * 32 + lane;
                const int j  = j0 + jt;
                float d1 = 0.f, d2 = 0.f;
#pragma unroll
                for (int k = 0; k < DIM; k++) {
                    d1 = fmaf(rP[k], tQ[k][jt], d1);
                    d2 = fmaf(rQ[k], tP[k][jt], d2);
                }
                float a   = d1 - d2;
                float val = xla_tanh(ALPHA * a);
                bool pred = (j < N_NODES) && (val >= C);
                unsigned m = __ballot_sync(0xffffffffu, pred);
                int rank = __popc(m & ((1u << lane) - 1u));
                if (pred && (hits + rank) < KSEL)
                    out[(size_t)row * N_NODES + j] = val;   // own row, already zeroed
                hits += __popc(m);
                if (hits >= KSEL) break;
            }
            if (hits >= KSEL) {
                done = true;
                if (lane == 0) atomicAdd(&s_done, 1);
            }
        }
        __syncthreads();
        if (s_done == RPB) break;
    }

    if (hits < KSEL && lane == 0) {
        int slot = atomicAdd(&g_nfail, 1);
        g_fail[slot] = row;
    }

    // ---- phase 5: last block resets claim/gate counters for next replay ----
    __syncthreads();
    if (tid == 0) {
        int t = atomicAdd(&g_c2, 1);
        if (t == NGROUPS - 1) { g_claim = 0; g_c1 = 0; g_c2 = 0; }
    }
}

// ---------------- fallback: exact stable top-32, 1 block (expected no-op) ----------------
__global__ void __launch_bounds__(256) fallback_kernel(float* __restrict__ out) {
    const int tid = threadIdx.x, lane = tid & 31, w = tid >> 5;
    constexpr int CPT = (N_NODES + 255) / 256;

    __shared__ unsigned long long warpmax[8];
    __shared__ unsigned long long s_best;

    const int nfail = g_nfail;
    for (int t = 0; t < nfail; t++) {
        const int frow = g_fail[t];
        float rP[DIM], rQ[DIM];
#pragma unroll
        for (int k = 0; k < DIM; k++) {
            rP[k] = g_P[frow * DIM + k];
            rQ[k] = g_Q[frow * DIM + k];
        }
        float vals[CPT];
#pragma unroll
        for (int c = 0; c < CPT; c++) {
            int j = tid + c * 256;
            float v = -1.f;
            if (j < N_NODES) {
                float d1 = 0.f, d2 = 0.f;
                for (int k = 0; k < DIM; k++) {
                    d1 = fmaf(rP[k], g_Q[j * DIM + k], d1);
                    d2 = fmaf(rQ[k], g_P[j * DIM + k], d2);
                }
                v = fmaxf(0.f, xla_tanh(ALPHA * (d1 - d2)));
            }
            vals[c] = v;
        }
        unsigned long long chosen = 0ull;
        for (int it = 0; it < KSEL; it++) {
            unsigned long long best = 0ull;
#pragma unroll
            for (int c = 0; c < CPT; c++) {
                int j = tid + c * 256;
                if (j < N_NODES && !((chosen >> c) & 1ull) && vals[c] >= 0.f) {
                    unsigned long long key =
                        ((unsigned long long)__float_as_uint(vals[c]) << 32) |
                        (unsigned long long)(0xFFFFFFFFu - (unsigned)j);
                    if (key > best) best = key;
                }
            }
#pragma unroll
            for (int off = 16; off > 0; off >>= 1) {
                unsigned long long o = __shfl_down_sync(0xffffffffu, best, off);
                if (o > best) best = o;
            }
            if (lane == 0) warpmax[w] = best;
            __syncthreads();
            if (tid == 0) {
                unsigned long long b = warpmax[0];
                for (int i = 1; i < 8; i++) if (warpmax[i] > b) b = warpmax[i];
                s_best = b;
            }
            __syncthreads();
            unsigned long long gb = s_best;
            int widx = (int)(0xFFFFFFFFu - (unsigned)(gb & 0xFFFFFFFFu));
            if ((widx & 255) == tid) {
                chosen |= 1ull << (widx >> 8);
                out[(size_t)frow * N_NODES + widx] = __uint_as_float((unsigned)(gb >> 32));
            }
            __syncthreads();
        }
        __syncthreads();
    }
    __syncthreads();
    if (tid == 0) g_nfail = 0;   // reset for next replay
}

// ---------------- launch ----------------
extern "C" void kernel_launch(void* const* d_in, const int* in_sizes, int n_in,
                              void* d_out, int out_size) {
    const int*   idx  = (const int*)  d_in[0];
    const float* emb1 = (const float*)d_in[1];
    const float* emb2 = (const float*)d_in[2];
    const float* W1   = (const float*)d_in[3];
    const float* b1   = (const float*)d_in[4];
    const float* W2   = (const float*)d_in[5];
    const float* b2   = (const float*)d_in[6];
    float* out = (float*)d_out;

    (void)in_sizes; (void)n_in; (void)out_size;

    mega_kernel<<<NGROUPS, 256>>>(idx, emb1, emb2, W1, b1, W2, b2, out);
    fallback_kernel<<<1, 256>>>(out);
}